// round 12
// baseline (speedup 1.0000x reference)
#include <cuda_runtime.h>
#include <cuda_fp16.h>
#include <cstdint>

// Problem constants: B=2,H=16,N=4096,D=64,F=256
#define BHp   32
#define Np    4096
#define Dp    64
#define Fp    256
#define CHUNK 64
#define GROUPS 16
#define ROWS_PER_GROUP 256
#define CHUNKS_PER_GROUP 4
#define NJOBS (BHp * GROUPS)
#define NCTA  148
#define NT    512

// smem strides (in halves)
#define XS_S  72
#define PT_S  72
#define VT_S  72
#define KPT_S 72
#define QP_S  264
#define KVT_S 264

// smem byte offsets
#define OFF_PTH   0u
#define OFF_PTL   36864u
#define U0        73728u
#define OFF_SK    (U0)
#define OFF_SV    (U0 + 16384u)
#define OFF_SQ    (U0)
#define OFF_XSH   (U0 + 32768u)
#define OFF_XSL   (U0 + 41984u)
#define OFF_VT    (U0 + 51200u)
#define OFF_KPT   (U0 + 60416u)
#define OFF_RMK   (U0 + 97280u)    // [4][64] f32 = 1024 B
#define OFF_QP    (U0 + 51200u)
#define OFF_KVT   (U0 + 84992u)
#define OFF_KSS   (U0 + 118784u)
#define OFF_RMQ   (U0 + 119808u)   // [4][64] f32
#define OFF_DNI   (U0 + 120832u)
#define SMEM_TOTAL (U0 + 121088u)  // 194816 B

__device__ float g_kv[BHp * Fp * Dp];
__device__ float g_ksum[BHp * Fp];
__device__ unsigned g_sync[BHp];
__device__ unsigned g_jobk;
__device__ unsigned g_jobq;

__global__ void zero_scratch() {
    int i = blockIdx.x * blockDim.x + threadIdx.x;
    if (i < BHp * Fp * Dp) g_kv[i] = 0.0f;
    if (i < BHp * Fp)      g_ksum[i] = 0.0f;
    if (i < BHp)           g_sync[i] = 0u;
    if (i == 0) { g_jobk = 0u; g_jobq = 0u; }
}

__device__ __forceinline__ void mma16816(float* c,
                                         unsigned a0, unsigned a1, unsigned a2, unsigned a3,
                                         unsigned b0, unsigned b1) {
    asm volatile(
        "mma.sync.aligned.m16n8k16.row.col.f32.f16.f16.f32 "
        "{%0,%1,%2,%3},{%4,%5,%6,%7},{%8,%9},{%0,%1,%2,%3};"
        : "+f"(c[0]), "+f"(c[1]), "+f"(c[2]), "+f"(c[3])
        : "r"(a0), "r"(a1), "r"(a2), "r"(a3), "r"(b0), "r"(b1));
}
__device__ __forceinline__ unsigned lds_u32(const __half* p) { return *(const unsigned*)p; }

__device__ __forceinline__ void cpasync16(void* dst_smem, const void* src) {
    uint32_t d = (uint32_t)__cvta_generic_to_shared(dst_smem);
    asm volatile("cp.async.cg.shared.global [%0], [%1], 16;" :: "r"(d), "l"(src));
}
#define CP_COMMIT() asm volatile("cp.async.commit_group;" ::: "memory")
#define CP_WAIT0()  asm volatile("cp.async.wait_group 0;" ::: "memory")

__device__ __forceinline__ void load_PT(const float* __restrict__ P,
                                        __half* PTh, __half* PTl, int tid) {
    for (int j = tid; j < Dp * Fp / 4; j += NT) {
        float4 v = ((const float4*)P)[j];
        int d = j >> 6;
        int f0 = (j & 63) * 4;
        #pragma unroll
        for (int u = 0; u < 4; u++) {
            float x = (&v.x)[u];
            __half hi = __float2half_rn(x);
            __half lo = __float2half_rn(x - __half2float(hi));
            PTh[(f0 + u) * PT_S + d] = hi;
            PTl[(f0 + u) * PT_S + d] = lo;
        }
    }
}

// 3-term split projection over 8 f-tiles: rows [m0,m0+16), features [fbase,fbase+64)
__device__ __forceinline__ void proj_mma(const __half* XSh, const __half* XSl,
                                         const __half* PTh, const __half* PTl,
                                         int m0, int fbase, int lane,
                                         float pr[8][4]) {
    #pragma unroll
    for (int t = 0; t < 8; t++) {
        pr[t][0] = 0.f; pr[t][1] = 0.f; pr[t][2] = 0.f; pr[t][3] = 0.f;
    }
    const int r  = lane >> 2;
    const int q2 = (lane & 3) * 2;
    #pragma unroll
    for (int k0 = 0; k0 < 64; k0 += 16) {
        const int ar0 = (m0 + r) * XS_S + k0 + q2;
        const int ar1 = (m0 + r + 8) * XS_S + k0 + q2;
        unsigned ah0 = lds_u32(XSh + ar0);
        unsigned ah1 = lds_u32(XSh + ar1);
        unsigned ah2 = lds_u32(XSh + ar0 + 8);
        unsigned ah3 = lds_u32(XSh + ar1 + 8);
        unsigned al0 = lds_u32(XSl + ar0);
        unsigned al1 = lds_u32(XSl + ar1);
        unsigned al2 = lds_u32(XSl + ar0 + 8);
        unsigned al3 = lds_u32(XSl + ar1 + 8);
        #pragma unroll
        for (int t = 0; t < 8; t++) {
            const int fb = (fbase + t * 8 + r) * PT_S + k0 + q2;
            unsigned bh0 = lds_u32(PTh + fb);
            unsigned bh1 = lds_u32(PTh + fb + 8);
            unsigned bl0 = lds_u32(PTl + fb);
            unsigned bl1 = lds_u32(PTl + fb + 8);
            mma16816(pr[t], ah0, ah1, ah2, ah3, bh0, bh1);
            mma16816(pr[t], ah0, ah1, ah2, ah3, bl0, bl1);
            mma16816(pr[t], al0, al1, al2, al3, bh0, bh1);
        }
    }
}

// Row-max partials for one f-segment -> RMAX[seg][64]
__device__ __forceinline__ void rowmax_store(float pr[8][4], float* RMAX,
                                             int m0, int seg, int lane) {
    const int r = lane >> 2;
    float mlo = -3.4e38f, mhi = -3.4e38f;
    #pragma unroll
    for (int t = 0; t < 8; t++) {
        mlo = fmaxf(mlo, fmaxf(pr[t][0], pr[t][1]));
        mhi = fmaxf(mhi, fmaxf(pr[t][2], pr[t][3]));
    }
    #pragma unroll
    for (int off = 1; off <= 2; off <<= 1) {
        mlo = fmaxf(mlo, __shfl_xor_sync(0xffffffffu, mlo, off));
        mhi = fmaxf(mhi, __shfl_xor_sync(0xffffffffu, mhi, off));
    }
    if ((lane & 3) == 0) {
        RMAX[seg * 64 + m0 + r]     = mlo;
        RMAX[seg * 64 + m0 + 8 + r] = mhi;
    }
}

__device__ __forceinline__ float rmax4(const float* RMAX, int row) {
    return fmaxf(fmaxf(RMAX[row], RMAX[64 + row]),
                 fmaxf(RMAX[128 + row], RMAX[192 + row]));
}

// ---------------------------------------------------------------------------
__device__ void kside_job(const float* __restrict__ K, const float* __restrict__ V,
                          int pair, int grp, char* sm,
                          int tid, int w, int lane) {
    __half* PTh = (__half*)(sm + OFF_PTH);
    __half* PTl = (__half*)(sm + OFF_PTL);
    __half* XSh = (__half*)(sm + OFF_XSH);
    __half* XSl = (__half*)(sm + OFF_XSL);
    __half* VT  = (__half*)(sm + OFF_VT);
    __half* KPT = (__half*)(sm + OFF_KPT);
    float*  RMAX = (float*)(sm + OFF_RMK);
    float4* SK = (float4*)(sm + OFF_SK);
    float4* SV = (float4*)(sm + OFF_SV);

    const int r  = lane >> 2;
    const int q2 = (lane & 3) * 2;

    {
        const float4* ksrc = (const float4*)(K + ((size_t)pair * Np + grp * ROWS_PER_GROUP) * Dp);
        const float4* vsrc = (const float4*)(V + ((size_t)pair * Np + grp * ROWS_PER_GROUP) * Dp);
        #pragma unroll
        for (int i = 0; i < 2; i++) {
            int j = tid + NT * i;
            cpasync16(&SK[j], &ksrc[j]);
            cpasync16(&SV[j], &vsrc[j]);
        }
        CP_COMMIT();
    }

    // warp owns f-tile [w*16, w*16+16) of kv
    float accv[8][4];
    #pragma unroll
    for (int t = 0; t < 8; t++)
        #pragma unroll
        for (int u = 0; u < 4; u++) accv[t][u] = 0.f;
    float ksp = 0.f;

    for (int c = 0; c < CHUNKS_PER_GROUP; c++) {
        CP_WAIT0();
        __syncthreads();

        #pragma unroll
        for (int i = 0; i < 2; i++) {
            int j = tid + NT * i;
            float4 xv = SK[j];
            float4 vv = SV[j];
            int rr = j >> 4;
            int d0 = (j & 15) * 4;
            #pragma unroll
            for (int u = 0; u < 4; u++) {
                float x = (&xv.x)[u];
                __half hi = __float2half_rn(x);
                __half lo = __float2half_rn(x - __half2float(hi));
                XSh[rr * XS_S + d0 + u] = hi;
                XSl[rr * XS_S + d0 + u] = lo;
                VT[(d0 + u) * VT_S + rr] = __float2half_rn((&vv.x)[u]);
            }
        }
        __syncthreads();

        if (c + 1 < CHUNKS_PER_GROUP) {
            const int row1 = grp * ROWS_PER_GROUP + (c + 1) * CHUNK;
            const float4* ksrc = (const float4*)(K + ((size_t)pair * Np + row1) * Dp);
            const float4* vsrc = (const float4*)(V + ((size_t)pair * Np + row1) * Dp);
            #pragma unroll
            for (int i = 0; i < 2; i++) {
                int j = tid + NT * i;
                cpasync16(&SK[j], &ksrc[j]);
                cpasync16(&SV[j], &vsrc[j]);
            }
            CP_COMMIT();
        }

        const int m0 = (w >> 2) * 16;
        const int seg = w & 3;
        const int fbase = seg * 64;
        float pr[8][4];
        proj_mma(XSh, XSl, PTh, PTl, m0, fbase, lane, pr);
        rowmax_store(pr, RMAX, m0, seg, lane);
        __syncthreads();

        {
            const float Mlo = rmax4(RMAX, m0 + r);
            const float Mhi = rmax4(RMAX, m0 + 8 + r);
            #pragma unroll
            for (int t = 0; t < 8; t++) {
                const int f = fbase + t * 8 + q2;
                KPT[f * KPT_S + m0 + r]           = __float2half_rn(__expf(pr[t][0] - Mlo) * 0.0625f);
                KPT[(f + 1) * KPT_S + m0 + r]     = __float2half_rn(__expf(pr[t][1] - Mlo) * 0.0625f);
                KPT[f * KPT_S + m0 + 8 + r]       = __float2half_rn(__expf(pr[t][2] - Mhi) * 0.0625f);
                KPT[(f + 1) * KPT_S + m0 + 8 + r] = __float2half_rn(__expf(pr[t][3] - Mhi) * 0.0625f);
            }
        }
        __syncthreads();

        // kv += k'^T v : warp w owns f-rows [w*16, w*16+16)
        const int fw = w * 16;
        #pragma unroll
        for (int k0 = 0; k0 < 64; k0 += 16) {
            const int base0 = (fw + r) * KPT_S + k0 + q2;
            const int base1 = (fw + 8 + r) * KPT_S + k0 + q2;
            unsigned a0 = lds_u32(KPT + base0);
            unsigned a1 = lds_u32(KPT + base1);
            unsigned a2 = lds_u32(KPT + base0 + 8);
            unsigned a3 = lds_u32(KPT + base1 + 8);
            #pragma unroll
            for (int t = 0; t < 8; t++) {
                const int vb = (t * 8 + r) * VT_S + k0 + q2;
                unsigned b0 = lds_u32(VT + vb);
                unsigned b1 = lds_u32(VT + vb + 8);
                mma16816(accv[t], a0, a1, a2, a3, b0, b1);
            }
        }

        if (tid < Fp) {
            const __half2* rowp = (const __half2*)(KPT + tid * KPT_S);
            float sx = 0.f, sy = 0.f;
            #pragma unroll
            for (int j = 0; j < 32; j++) {
                float2 f2 = __half22float2(rowp[j]);
                sx += f2.x; sy += f2.y;
            }
            ksp += sx + sy;
        }
    }

    float* kvg = g_kv + (size_t)pair * Fp * Dp;
    {
        const int f0 = w * 16 + r;
        #pragma unroll
        for (int t = 0; t < 8; t++) {
            const int e = t * 8 + q2;
            atomicAdd(&kvg[f0 * Dp + e],           accv[t][0]);
            atomicAdd(&kvg[f0 * Dp + e + 1],       accv[t][1]);
            atomicAdd(&kvg[(f0 + 8) * Dp + e],     accv[t][2]);
            atomicAdd(&kvg[(f0 + 8) * Dp + e + 1], accv[t][3]);
        }
    }
    if (tid < Fp) atomicAdd(&g_ksum[(size_t)pair * Fp + tid], ksp);

    __syncthreads();
    __threadfence();
    if (tid == 0) atomicAdd(&g_sync[pair], 1u);
}

// ---------------------------------------------------------------------------
__device__ void qside_job(const float* __restrict__ Q, float* __restrict__ out,
                          int pair, int grp, bool reload_kv, char* sm,
                          int tid, int w, int lane) {
    __half* PTh = (__half*)(sm + OFF_PTH);
    __half* PTl = (__half*)(sm + OFF_PTL);
    __half* XSh = (__half*)(sm + OFF_XSH);
    __half* XSl = (__half*)(sm + OFF_XSL);
    __half* QP  = (__half*)(sm + OFF_QP);
    __half* KVTh = (__half*)(sm + OFF_KVT);
    float*  KSS  = (float*)(sm + OFF_KSS);
    float*  RMAX = (float*)(sm + OFF_RMQ);
    float*  DNI  = (float*)(sm + OFF_DNI);
    float4* SQ   = (float4*)(sm + OFF_SQ);

    const int r  = lane >> 2;
    const int q2 = (lane & 3) * 2;

    {
        const float4* qsrc = (const float4*)(Q + ((size_t)pair * Np + grp * ROWS_PER_GROUP) * Dp);
        #pragma unroll
        for (int i = 0; i < 2; i++) {
            int j = tid + NT * i;
            cpasync16(&SQ[j], &qsrc[j]);
        }
        CP_COMMIT();
    }

    if (reload_kv) {
        const float4* kvg = (const float4*)(g_kv + (size_t)pair * Fp * Dp);
        for (int j = tid; j < Fp * Dp / 4; j += NT) {
            float4 v = __ldcg(&kvg[j]);
            int f = j >> 4;
            int e0 = (j & 15) * 4;
            #pragma unroll
            for (int u = 0; u < 4; u++)
                KVTh[(e0 + u) * KVT_S + f] = __float2half_rn((&v.x)[u]);
        }
        if (tid < Fp) KSS[tid] = __ldcg(&g_ksum[(size_t)pair * Fp + tid]) + 1e-6f;
    }

    for (int c = 0; c < CHUNKS_PER_GROUP; c++) {
        CP_WAIT0();
        __syncthreads();

        #pragma unroll
        for (int i = 0; i < 2; i++) {
            int j = tid + NT * i;
            float4 xv = SQ[j];
            int rr = j >> 4;
            int d0 = (j & 15) * 4;
            #pragma unroll
            for (int u = 0; u < 4; u++) {
                float x = (&xv.x)[u];
                __half hi = __float2half_rn(x);
                __half lo = __float2half_rn(x - __half2float(hi));
                XSh[rr * XS_S + d0 + u] = hi;
                XSl[rr * XS_S + d0 + u] = lo;
            }
        }
        __syncthreads();

        if (c + 1 < CHUNKS_PER_GROUP) {
            const int row1 = grp * ROWS_PER_GROUP + (c + 1) * CHUNK;
            const float4* qsrc = (const float4*)(Q + ((size_t)pair * Np + row1) * Dp);
            #pragma unroll
            for (int i = 0; i < 2; i++) {
                int j = tid + NT * i;
                cpasync16(&SQ[j], &qsrc[j]);
            }
            CP_COMMIT();
        }

        const int m0 = (w >> 2) * 16;
        const int seg = w & 3;
        const int fbase = seg * 64;
        float pr[8][4];
        proj_mma(XSh, XSl, PTh, PTl, m0, fbase, lane, pr);
        rowmax_store(pr, RMAX, m0, seg, lane);
        __syncthreads();

        {
            const float Mlo = rmax4(RMAX, m0 + r);
            const float Mhi = rmax4(RMAX, m0 + 8 + r);
            #pragma unroll
            for (int t = 0; t < 8; t++) {
                const int f = fbase + t * 8 + q2;
                __half2 lo2 = __floats2half2_rn(__expf(pr[t][0] - Mlo) * 0.0625f,
                                                __expf(pr[t][1] - Mlo) * 0.0625f);
                __half2 hi2 = __floats2half2_rn(__expf(pr[t][2] - Mhi) * 0.0625f,
                                                __expf(pr[t][3] - Mhi) * 0.0625f);
                *(__half2*)(QP + (m0 + r) * QP_S + f)     = lo2;
                *(__half2*)(QP + (m0 + 8 + r) * QP_S + f) = hi2;
            }
        }
        __syncthreads();

        // denom: warp w owns rows [w*4, w*4+4)
        {
            #pragma unroll
            for (int rr = 0; rr < 4; rr++) {
                const int row = w * 4 + rr;
                float s = 0.f;
                #pragma unroll
                for (int j = 0; j < 8; j++) {
                    const int f = lane + 32 * j;
                    s = fmaf(__half2float(QP[row * QP_S + f]), KSS[f], s);
                }
                #pragma unroll
                for (int off = 16; off > 0; off >>= 1)
                    s += __shfl_xor_sync(0xffffffffu, s, off);
                if (lane == 0) DNI[row] = 1.0f / s;
            }
        }

        // out mma: rows [om0,om0+16), cols [nb,nb+16)
        const int om0 = (w >> 2) * 16;
        const int nb  = (w & 3) * 16;
        float oc[2][4];
        #pragma unroll
        for (int t = 0; t < 2; t++)
            #pragma unroll
            for (int u = 0; u < 4; u++) oc[t][u] = 0.f;

        #pragma unroll
        for (int k0 = 0; k0 < 256; k0 += 16) {
            const int ab0 = (om0 + r) * QP_S + k0 + q2;
            const int ab1 = (om0 + 8 + r) * QP_S + k0 + q2;
            unsigned a0 = lds_u32(QP + ab0);
            unsigned a1 = lds_u32(QP + ab1);
            unsigned a2 = lds_u32(QP + ab0 + 8);
            unsigned a3 = lds_u32(QP + ab1 + 8);
            #pragma unroll
            for (int t = 0; t < 2; t++) {
                const int bb = (nb + t * 8 + r) * KVT_S + k0 + q2;
                unsigned bh0 = lds_u32(KVTh + bb);
                unsigned bh1 = lds_u32(KVTh + bb + 8);
                mma16816(oc[t], a0, a1, a2, a3, bh0, bh1);
            }
        }
        __syncthreads();   // DNI visible

        float* od = out + ((size_t)pair * Np + grp * ROWS_PER_GROUP + c * CHUNK) * Dp;
        const float ilo = DNI[om0 + r];
        const float ihi = DNI[om0 + 8 + r];
        #pragma unroll
        for (int t = 0; t < 2; t++) {
            const int e = nb + t * 8 + q2;
            float2 v0 = make_float2(oc[t][0] * ilo, oc[t][1] * ilo);
            float2 v1 = make_float2(oc[t][2] * ihi, oc[t][3] * ihi);
            *(float2*)&od[(om0 + r) * Dp + e]     = v0;
            *(float2*)&od[(om0 + 8 + r) * Dp + e] = v1;
        }
    }
}

// ---------------------------------------------------------------------------
__global__ __launch_bounds__(NT, 1)
void fused_kernel(const float* __restrict__ Q, const float* __restrict__ K,
                  const float* __restrict__ V, const float* __restrict__ P,
                  float* __restrict__ out) {
    extern __shared__ char sm[];
    __shared__ int jobS;

    const int tid  = threadIdx.x;
    const int w    = tid >> 5;
    const int lane = tid & 31;

    load_PT(P, (__half*)(sm + OFF_PTH), (__half*)(sm + OFF_PTL), tid);
    __syncthreads();

    // phase 1: kside
    for (;;) {
        if (tid == 0) jobS = (int)atomicAdd(&g_jobk, 1u);
        __syncthreads();
        const int j = jobS;
        if (j >= NJOBS) break;
        kside_job(K, V, j / GROUPS, j % GROUPS, sm, tid, w, lane);
        __syncthreads();
    }

    // phase 2: qside
    int prev_pair = -1;
    for (;;) {
        if (tid == 0) jobS = (int)atomicAdd(&g_jobq, 1u);
        __syncthreads();
        const int j = jobS;
        if (j >= NJOBS) break;
        const int pair = j / GROUPS;
        const int grp  = j % GROUPS;
        const bool reload = (pair != prev_pair);
        if (reload) {
            if (tid == 0) {
                while (atomicAdd(&g_sync[pair], 0u) < (unsigned)GROUPS) __nanosleep(100);
            }
            __syncthreads();
            __threadfence();
            prev_pair = pair;
        }
        qside_job(Q, out, pair, grp, reload, sm, tid, w, lane);
        __syncthreads();
    }
}

// ---------------------------------------------------------------------------
extern "C" void kernel_launch(void* const* d_in, const int* in_sizes, int n_in,
                              void* d_out, int out_size) {
    const float* q = (const float*)d_in[0];
    const float* k = (const float*)d_in[1];
    const float* v = (const float*)d_in[2];
    const float* p = (const float*)d_in[3];
    float* out = (float*)d_out;

    cudaFuncSetAttribute(fused_kernel, cudaFuncAttributeMaxDynamicSharedMemorySize, (int)SMEM_TOTAL);

    {
        int total = BHp * Fp * Dp;
        zero_scratch<<<(total + 255) / 256, 256>>>();
    }
    fused_kernel<<<NCTA, NT, SMEM_TOTAL>>>(q, k, v, p, out);
}

// round 13
// speedup vs baseline: 1.0062x; 1.0062x over previous
#include <cuda_runtime.h>
#include <cuda_fp16.h>
#include <cstdint>

// Problem constants: B=2,H=16,N=4096,D=64,F=256
#define BHp   32
#define Np    4096
#define Dp    64
#define Fp    256
#define CHUNK 64
#define GROUPS 16
#define ROWS_PER_GROUP 256
#define CHUNKS_PER_GROUP 4
#define NJOBS (BHp * GROUPS)
#define NCTA  148
#define NT    256

// smem strides (in halves)
#define XS_S  72
#define PT_S  72
#define VT_S  72
#define KPT_S 72
#define QP_S  264
#define KVT_S 264

// smem byte offsets
#define OFF_PTH   0u
#define OFF_PTL   36864u
#define U0        73728u
#define OFF_SK    (U0)
#define OFF_SV    (U0 + 16384u)
#define OFF_SQ    (U0)
#define OFF_XSH   (U0 + 32768u)
#define OFF_XSL   (U0 + 41984u)
#define OFF_VT    (U0 + 51200u)
#define OFF_KPT   (U0 + 60416u)
#define OFF_RMK   (U0 + 97280u)    // [4][64] f32
#define OFF_QP    (U0 + 51200u)
#define OFF_KVT   (U0 + 84992u)
#define OFF_KSS   (U0 + 118784u)
#define OFF_RMQ   (U0 + 119808u)   // [4][64] f32
#define OFF_DNI   (U0 + 120832u)
#define SMEM_TOTAL (U0 + 121088u)

__device__ float g_kv[BHp * Fp * Dp];
__device__ float g_ksum[BHp * Fp];
__device__ unsigned g_sync[BHp];
__device__ unsigned g_jobk;
__device__ unsigned g_jobq;

__global__ void zero_scratch() {
    int i = blockIdx.x * blockDim.x + threadIdx.x;
    if (i < BHp * Fp * Dp) g_kv[i] = 0.0f;
    if (i < BHp * Fp)      g_ksum[i] = 0.0f;
    if (i < BHp)           g_sync[i] = 0u;
    if (i == 0) { g_jobk = 0u; g_jobq = 0u; }
}

__device__ __forceinline__ void mma16816(float* c,
                                         unsigned a0, unsigned a1, unsigned a2, unsigned a3,
                                         unsigned b0, unsigned b1) {
    asm volatile(
        "mma.sync.aligned.m16n8k16.row.col.f32.f16.f16.f32 "
        "{%0,%1,%2,%3},{%4,%5,%6,%7},{%8,%9},{%0,%1,%2,%3};"
        : "+f"(c[0]), "+f"(c[1]), "+f"(c[2]), "+f"(c[3])
        : "r"(a0), "r"(a1), "r"(a2), "r"(a3), "r"(b0), "r"(b1));
}
__device__ __forceinline__ void ldsm4(unsigned* r, uint32_t a) {
    asm volatile("ldmatrix.sync.aligned.m8n8.x4.shared.b16 {%0,%1,%2,%3}, [%4];"
        : "=r"(r[0]), "=r"(r[1]), "=r"(r[2]), "=r"(r[3]) : "r"(a));
}
__device__ __forceinline__ void ldsm2(unsigned* r, uint32_t a) {
    asm volatile("ldmatrix.sync.aligned.m8n8.x2.shared.b16 {%0,%1}, [%2];"
        : "=r"(r[0]), "=r"(r[1]) : "r"(a));
}

__device__ __forceinline__ void cpasync16(void* dst_smem, const void* src) {
    uint32_t d = (uint32_t)__cvta_generic_to_shared(dst_smem);
    asm volatile("cp.async.cg.shared.global [%0], [%1], 16;" :: "r"(d), "l"(src));
}
#define CP_COMMIT() asm volatile("cp.async.commit_group;" ::: "memory")
#define CP_WAIT0()  asm volatile("cp.async.wait_group 0;" ::: "memory")

__device__ __forceinline__ void load_PT(const float* __restrict__ P,
                                        __half* PTh, __half* PTl, int tid) {
    for (int j = tid; j < Dp * Fp / 4; j += NT) {
        float4 v = ((const float4*)P)[j];
        int d = j >> 6;
        int f0 = (j & 63) * 4;
        #pragma unroll
        for (int u = 0; u < 4; u++) {
            float x = (&v.x)[u];
            __half hi = __float2half_rn(x);
            __half lo = __float2half_rn(x - __half2float(hi));
            PTh[(f0 + u) * PT_S + d] = hi;
            PTl[(f0 + u) * PT_S + d] = lo;
        }
    }
}

// ldmatrix lane-constant byte offsets for stride S (in halves)
__device__ __forceinline__ int a4_const(int lane, int S) {
    return 2 * (((lane & 7) + ((lane >> 3) & 1) * 8) * S + (lane >> 4) * 8);
}
__device__ __forceinline__ int b2_const(int lane, int S) {
    return 2 * ((lane & 7) * S + ((lane >> 3) & 1) * 8);
}

// 3-term projection, warp tile m32 x f64, ldmatrix loads
__device__ __forceinline__ void proj_mma(uint32_t xsh, uint32_t xsl,
                                         uint32_t pth, uint32_t ptl,
                                         int m0, int fbase, int a4c, int b2c,
                                         float pr[2][8][4]) {
    #pragma unroll
    for (int mi = 0; mi < 2; mi++)
        #pragma unroll
        for (int t = 0; t < 8; t++) {
            pr[mi][t][0] = 0.f; pr[mi][t][1] = 0.f; pr[mi][t][2] = 0.f; pr[mi][t][3] = 0.f;
        }
    #pragma unroll
    for (int k0 = 0; k0 < 64; k0 += 16) {
        unsigned ah[2][4], al[2][4];
        #pragma unroll
        for (int mi = 0; mi < 2; mi++) {
            uint32_t ab = 2u * ((m0 + mi * 16) * XS_S + k0) + a4c;
            ldsm4(ah[mi], xsh + ab);
            ldsm4(al[mi], xsl + ab);
        }
        #pragma unroll
        for (int t = 0; t < 8; t++) {
            uint32_t bb = 2u * ((fbase + t * 8) * PT_S + k0) + b2c;
            unsigned bh[2], bl[2];
            ldsm2(bh, pth + bb);
            ldsm2(bl, ptl + bb);
            #pragma unroll
            for (int mi = 0; mi < 2; mi++) {
                mma16816(pr[mi][t], ah[mi][0], ah[mi][1], ah[mi][2], ah[mi][3], bh[0], bh[1]);
                mma16816(pr[mi][t], ah[mi][0], ah[mi][1], ah[mi][2], ah[mi][3], bl[0], bl[1]);
                mma16816(pr[mi][t], al[mi][0], al[mi][1], al[mi][2], al[mi][3], bh[0], bh[1]);
            }
        }
    }
}

// Row-max partials for one f-segment (seg) over m32 tile -> RMAX[seg][64]
__device__ __forceinline__ void rowmax_store(float pr[2][8][4], float* RMAX,
                                             int m0, int seg, int lane) {
    const int r = lane >> 2;
    #pragma unroll
    for (int mi = 0; mi < 2; mi++) {
        float mlo = -3.4e38f, mhi = -3.4e38f;
        #pragma unroll
        for (int t = 0; t < 8; t++) {
            mlo = fmaxf(mlo, fmaxf(pr[mi][t][0], pr[mi][t][1]));
            mhi = fmaxf(mhi, fmaxf(pr[mi][t][2], pr[mi][t][3]));
        }
        #pragma unroll
        for (int off = 1; off <= 2; off <<= 1) {
            mlo = fmaxf(mlo, __shfl_xor_sync(0xffffffffu, mlo, off));
            mhi = fmaxf(mhi, __shfl_xor_sync(0xffffffffu, mhi, off));
        }
        if ((lane & 3) == 0) {
            RMAX[seg * 64 + m0 + mi * 16 + r]     = mlo;
            RMAX[seg * 64 + m0 + mi * 16 + 8 + r] = mhi;
        }
    }
}

__device__ __forceinline__ float rmax4(const float* RMAX, int row) {
    return fmaxf(fmaxf(RMAX[row], RMAX[64 + row]),
                 fmaxf(RMAX[128 + row], RMAX[192 + row]));
}

// ---------------------------------------------------------------------------
__device__ void kside_job(const float* __restrict__ K, const float* __restrict__ V,
                          int pair, int grp, char* sm, uint32_t smu,
                          int tid, int w, int lane) {
    __half* XSh = (__half*)(sm + OFF_XSH);
    __half* XSl = (__half*)(sm + OFF_XSL);
    __half* VT  = (__half*)(sm + OFF_VT);
    __half* KPT = (__half*)(sm + OFF_KPT);
    float*  RMAX = (float*)(sm + OFF_RMK);
    float4* SK = (float4*)(sm + OFF_SK);
    float4* SV = (float4*)(sm + OFF_SV);

    const uint32_t xsh_u = smu + OFF_XSH, xsl_u = smu + OFF_XSL;
    const uint32_t pth_u = smu + OFF_PTH, ptl_u = smu + OFF_PTL;
    const uint32_t vt_u  = smu + OFF_VT,  kpt_u = smu + OFF_KPT;

    const int r  = lane >> 2;
    const int q2 = (lane & 3) * 2;
    const int a4c72 = a4_const(lane, 72);
    const int b2c72 = b2_const(lane, 72);

    {
        const float4* ksrc = (const float4*)(K + ((size_t)pair * Np + grp * ROWS_PER_GROUP) * Dp);
        const float4* vsrc = (const float4*)(V + ((size_t)pair * Np + grp * ROWS_PER_GROUP) * Dp);
        #pragma unroll
        for (int i = 0; i < 4; i++) {
            int j = tid + NT * i;
            cpasync16(&SK[j], &ksrc[j]);
            cpasync16(&SV[j], &vsrc[j]);
        }
        CP_COMMIT();
    }

    // warp owns kv f-rows [w*32, w*32+32)
    float accv[2][8][4];
    #pragma unroll
    for (int mi = 0; mi < 2; mi++)
        #pragma unroll
        for (int t = 0; t < 8; t++)
            #pragma unroll
            for (int u = 0; u < 4; u++) accv[mi][t][u] = 0.f;
    float ksp = 0.f;

    for (int c = 0; c < CHUNKS_PER_GROUP; c++) {
        CP_WAIT0();
        __syncthreads();

        #pragma unroll
        for (int i = 0; i < 4; i++) {
            int j = tid + NT * i;
            float4 xv = SK[j];
            float4 vv = SV[j];
            int rr = j >> 4;
            int d0 = (j & 15) * 4;
            #pragma unroll
            for (int u = 0; u < 4; u++) {
                float x = (&xv.x)[u];
                __half hi = __float2half_rn(x);
                __half lo = __float2half_rn(x - __half2float(hi));
                XSh[rr * XS_S + d0 + u] = hi;
                XSl[rr * XS_S + d0 + u] = lo;
                VT[(d0 + u) * VT_S + rr] = __float2half_rn((&vv.x)[u]);
            }
        }
        __syncthreads();

        if (c + 1 < CHUNKS_PER_GROUP) {
            const int row1 = grp * ROWS_PER_GROUP + (c + 1) * CHUNK;
            const float4* ksrc = (const float4*)(K + ((size_t)pair * Np + row1) * Dp);
            const float4* vsrc = (const float4*)(V + ((size_t)pair * Np + row1) * Dp);
            #pragma unroll
            for (int i = 0; i < 4; i++) {
                int j = tid + NT * i;
                cpasync16(&SK[j], &ksrc[j]);
                cpasync16(&SV[j], &vsrc[j]);
            }
            CP_COMMIT();
        }

        const int m0 = (w >> 2) * 32;
        const int seg = w & 3;
        const int fbase = seg * 64;
        float pr[2][8][4];
        proj_mma(xsh_u, xsl_u, pth_u, ptl_u, m0, fbase, a4c72, b2c72, pr);
        rowmax_store(pr, RMAX, m0, seg, lane);
        __syncthreads();

        // exp + transposed store into KPT[f][row]
        #pragma unroll
        for (int mi = 0; mi < 2; mi++) {
            const int mrow = m0 + mi * 16;
            const float Mlo = rmax4(RMAX, mrow + r);
            const float Mhi = rmax4(RMAX, mrow + 8 + r);
            #pragma unroll
            for (int t = 0; t < 8; t++) {
                const int f = fbase + t * 8 + q2;
                KPT[f * KPT_S + mrow + r]           = __float2half_rn(__expf(pr[mi][t][0] - Mlo) * 0.0625f);
                KPT[(f + 1) * KPT_S + mrow + r]     = __float2half_rn(__expf(pr[mi][t][1] - Mlo) * 0.0625f);
                KPT[f * KPT_S + mrow + 8 + r]       = __float2half_rn(__expf(pr[mi][t][2] - Mhi) * 0.0625f);
                KPT[(f + 1) * KPT_S + mrow + 8 + r] = __float2half_rn(__expf(pr[mi][t][3] - Mhi) * 0.0625f);
            }
        }
        __syncthreads();

        // kv += k'^T v : warp owns f-rows [w*32, w*32+32)
        const int fw = w * 32;
        #pragma unroll
        for (int k0 = 0; k0 < 64; k0 += 16) {
            unsigned a[2][4];
            #pragma unroll
            for (int mi = 0; mi < 2; mi++)
                ldsm4(a[mi], kpt_u + 2u * ((fw + mi * 16) * KPT_S + k0) + a4c72);
            #pragma unroll
            for (int t = 0; t < 8; t++) {
                unsigned b[2];
                ldsm2(b, vt_u + 2u * ((t * 8) * VT_S + k0) + b2c72);
                mma16816(accv[0][t], a[0][0], a[0][1], a[0][2], a[0][3], b[0], b[1]);
                mma16816(accv[1][t], a[1][0], a[1][1], a[1][2], a[1][3], b[0], b[1]);
            }
        }

        // ksum partial: thread tid owns feature tid
        {
            const __half2* rowp = (const __half2*)(KPT + tid * KPT_S);
            float sx = 0.f, sy = 0.f;
            #pragma unroll
            for (int j = 0; j < 32; j++) {
                float2 f2 = __half22float2(rowp[j]);
                sx += f2.x; sy += f2.y;
            }
            ksp += sx + sy;
        }
    }

    float* kvg = g_kv + (size_t)pair * Fp * Dp;
    #pragma unroll
    for (int mi = 0; mi < 2; mi++) {
        const int f0 = w * 32 + mi * 16 + r;
        #pragma unroll
        for (int t = 0; t < 8; t++) {
            const int e = t * 8 + q2;
            atomicAdd(&kvg[f0 * Dp + e],           accv[mi][t][0]);
            atomicAdd(&kvg[f0 * Dp + e + 1],       accv[mi][t][1]);
            atomicAdd(&kvg[(f0 + 8) * Dp + e],     accv[mi][t][2]);
            atomicAdd(&kvg[(f0 + 8) * Dp + e + 1], accv[mi][t][3]);
        }
    }
    atomicAdd(&g_ksum[(size_t)pair * Fp + tid], ksp);

    __syncthreads();
    __threadfence();
    if (tid == 0) atomicAdd(&g_sync[pair], 1u);
}

// ---------------------------------------------------------------------------
__device__ void qside_job(const float* __restrict__ Q, float* __restrict__ out,
                          int pair, int grp, bool reload_kv, char* sm, uint32_t smu,
                          int tid, int w, int lane) {
    __half* XSh = (__half*)(sm + OFF_XSH);
    __half* XSl = (__half*)(sm + OFF_XSL);
    __half* QP  = (__half*)(sm + OFF_QP);
    __half* KVTh = (__half*)(sm + OFF_KVT);
    float*  KSS  = (float*)(sm + OFF_KSS);
    float*  RMAX = (float*)(sm + OFF_RMQ);
    float*  DNI  = (float*)(sm + OFF_DNI);
    float4* SQ   = (float4*)(sm + OFF_SQ);

    const uint32_t xsh_u = smu + OFF_XSH, xsl_u = smu + OFF_XSL;
    const uint32_t pth_u = smu + OFF_PTH, ptl_u = smu + OFF_PTL;
    const uint32_t qp_u  = smu + OFF_QP,  kvt_u = smu + OFF_KVT;

    const int r  = lane >> 2;
    const int q2 = (lane & 3) * 2;
    const int a4c72 = a4_const(lane, 72);
    const int b2c72 = b2_const(lane, 72);
    const int a4c264 = a4_const(lane, 264);
    const int b2c264 = b2_const(lane, 264);

    {
        const float4* qsrc = (const float4*)(Q + ((size_t)pair * Np + grp * ROWS_PER_GROUP) * Dp);
        #pragma unroll
        for (int i = 0; i < 4; i++) {
            int j = tid + NT * i;
            cpasync16(&SQ[j], &qsrc[j]);
        }
        CP_COMMIT();
    }

    if (reload_kv) {
        const float4* kvg = (const float4*)(g_kv + (size_t)pair * Fp * Dp);
        for (int j = tid; j < Fp * Dp / 4; j += NT) {
            float4 v = __ldcg(&kvg[j]);
            int f = j >> 4;
            int e0 = (j & 15) * 4;
            #pragma unroll
            for (int u = 0; u < 4; u++)
                KVTh[(e0 + u) * KVT_S + f] = __float2half_rn((&v.x)[u]);
        }
        KSS[tid] = __ldcg(&g_ksum[(size_t)pair * Fp + tid]) + 1e-6f;
    }

    for (int c = 0; c < CHUNKS_PER_GROUP; c++) {
        CP_WAIT0();
        __syncthreads();

        #pragma unroll
        for (int i = 0; i < 4; i++) {
            int j = tid + NT * i;
            float4 xv = SQ[j];
            int rr = j >> 4;
            int d0 = (j & 15) * 4;
            #pragma unroll
            for (int u = 0; u < 4; u++) {
                float x = (&xv.x)[u];
                __half hi = __float2half_rn(x);
                __half lo = __float2half_rn(x - __half2float(hi));
                XSh[rr * XS_S + d0 + u] = hi;
                XSl[rr * XS_S + d0 + u] = lo;
            }
        }
        __syncthreads();

        if (c + 1 < CHUNKS_PER_GROUP) {
            const int row1 = grp * ROWS_PER_GROUP + (c + 1) * CHUNK;
            const float4* qsrc = (const float4*)(Q + ((size_t)pair * Np + row1) * Dp);
            #pragma unroll
            for (int i = 0; i < 4; i++) {
                int j = tid + NT * i;
                cpasync16(&SQ[j], &qsrc[j]);
            }
            CP_COMMIT();
        }

        const int m0 = (w >> 2) * 32;
        const int seg = w & 3;
        const int fbase = seg * 64;
        float pr[2][8][4];
        proj_mma(xsh_u, xsl_u, pth_u, ptl_u, m0, fbase, a4c72, b2c72, pr);
        rowmax_store(pr, RMAX, m0, seg, lane);
        __syncthreads();

        // exp + row-major store QP[row][f] (half2)
        #pragma unroll
        for (int mi = 0; mi < 2; mi++) {
            const int mrow = m0 + mi * 16;
            const float Mlo = rmax4(RMAX, mrow + r);
            const float Mhi = rmax4(RMAX, mrow + 8 + r);
            #pragma unroll
            for (int t = 0; t < 8; t++) {
                const int f = fbase + t * 8 + q2;
                __half2 lo2 = __floats2half2_rn(__expf(pr[mi][t][0] - Mlo) * 0.0625f,
                                                __expf(pr[mi][t][1] - Mlo) * 0.0625f);
                __half2 hi2 = __floats2half2_rn(__expf(pr[mi][t][2] - Mhi) * 0.0625f,
                                                __expf(pr[mi][t][3] - Mhi) * 0.0625f);
                *(__half2*)(QP + (mrow + r) * QP_S + f)     = lo2;
                *(__half2*)(QP + (mrow + 8 + r) * QP_S + f) = hi2;
            }
        }
        __syncthreads();

        // denom: warp w owns rows w*8..w*8+7
        {
            #pragma unroll
            for (int rr = 0; rr < 8; rr++) {
                const int row = w * 8 + rr;
                float s = 0.f;
                #pragma unroll
                for (int j = 0; j < 8; j++) {
                    const int f = lane + 32 * j;
                    s = fmaf(__half2float(QP[row * QP_S + f]), KSS[f], s);
                }
                #pragma unroll
                for (int off = 16; off > 0; off >>= 1)
                    s += __shfl_xor_sync(0xffffffffu, s, off);
                if (lane == 0) DNI[row] = 1.0f / s;
            }
        }

        // out mma: rows [om0,om0+16), cols [nb,nb+32), ldmatrix loads
        const int om0 = (w >> 1) * 16;
        const int nb  = (w & 1) * 32;
        float oc[4][4];
        #pragma unroll
        for (int t = 0; t < 4; t++)
            #pragma unroll
            for (int u = 0; u < 4; u++) oc[t][u] = 0.f;

        #pragma unroll
        for (int k0 = 0; k0 < 256; k0 += 16) {
            unsigned a[4];
            ldsm4(a, qp_u + 2u * (om0 * QP_S + k0) + a4c264);
            #pragma unroll
            for (int t = 0; t < 4; t++) {
                unsigned b[2];
                ldsm2(b, kvt_u + 2u * ((nb + t * 8) * KVT_S + k0) + b2c264);
                mma16816(oc[t], a[0], a[1], a[2], a[3], b[0], b[1]);
            }
        }
        __syncthreads();   // DNI visible

        float* od = out + ((size_t)pair * Np + grp * ROWS_PER_GROUP + c * CHUNK) * Dp;
        const float ilo = DNI[om0 + r];
        const float ihi = DNI[om0 + 8 + r];
        #pragma unroll
        for (int t = 0; t < 4; t++) {
            const int e = nb + t * 8 + q2;
            float2 v0 = make_float2(oc[t][0] * ilo, oc[t][1] * ilo);
            float2 v1 = make_float2(oc[t][2] * ihi, oc[t][3] * ihi);
            *(float2*)&od[(om0 + r) * Dp + e]     = v0;
            *(float2*)&od[(om0 + 8 + r) * Dp + e] = v1;
        }
    }
}

// ---------------------------------------------------------------------------
__global__ __launch_bounds__(NT, 1)
void fused_kernel(const float* __restrict__ Q, const float* __restrict__ K,
                  const float* __restrict__ V, const float* __restrict__ P,
                  float* __restrict__ out) {
    extern __shared__ char sm[];
    __shared__ int jobS;

    const int tid  = threadIdx.x;
    const int w    = tid >> 5;
    const int lane = tid & 31;
    const uint32_t smu = (uint32_t)__cvta_generic_to_shared(sm);

    load_PT(P, (__half*)(sm + OFF_PTH), (__half*)(sm + OFF_PTL), tid);
    __syncthreads();

    // phase 1: kside
    for (;;) {
        if (tid == 0) jobS = (int)atomicAdd(&g_jobk, 1u);
        __syncthreads();
        const int j = jobS;
        if (j >= NJOBS) break;
        kside_job(K, V, j / GROUPS, j % GROUPS, sm, smu, tid, w, lane);
        __syncthreads();
    }

    // phase 2: qside
    int prev_pair = -1;
    for (;;) {
        if (tid == 0) jobS = (int)atomicAdd(&g_jobq, 1u);
        __syncthreads();
        const int j = jobS;
        if (j >= NJOBS) break;
        const int pair = j / GROUPS;
        const int grp  = j % GROUPS;
        const bool reload = (pair != prev_pair);
        if (reload) {
            if (tid == 0) {
                while (atomicAdd(&g_sync[pair], 0u) < (unsigned)GROUPS) __nanosleep(100);
            }
            __syncthreads();
            __threadfence();
            prev_pair = pair;
        }
        qside_job(Q, out, pair, grp, reload, sm, smu, tid, w, lane);
        __syncthreads();
    }
}

// ---------------------------------------------------------------------------
extern "C" void kernel_launch(void* const* d_in, const int* in_sizes, int n_in,
                              void* d_out, int out_size) {
    const float* q = (const float*)d_in[0];
    const float* k = (const float*)d_in[1];
    const float* v = (const float*)d_in[2];
    const float* p = (const float*)d_in[3];
    float* out = (float*)d_out;

    cudaFuncSetAttribute(fused_kernel, cudaFuncAttributeMaxDynamicSharedMemorySize, (int)SMEM_TOTAL);

    {
        int total = BHp * Fp * Dp;
        zero_scratch<<<(total + 255) / 256, 256>>>();
    }
    fused_kernel<<<NCTA, NT, SMEM_TOTAL>>>(q, k, v, p, out);
}

// round 14
// speedup vs baseline: 1.0646x; 1.0580x over previous
#include <cuda_runtime.h>
#include <cuda_fp16.h>
#include <cstdint>

// Problem constants: B=2,H=16,N=4096,D=64,F=256
#define BHp   32
#define Np    4096
#define Dp    64
#define Fp    256
#define CHUNK 64
#define GROUPS 16
#define ROWS_PER_GROUP 256
#define CHUNKS_PER_GROUP 4
#define NJOBS (BHp * GROUPS)
#define NCTA  148
#define NT    256

// smem strides (in halves)
#define XS_S  72
#define PT_S  72
#define V_S   72
#define KP_S  264
#define QP_S  264
#define KVT_S 264

// smem byte offsets
#define OFF_PTH   0u
#define OFF_PTL   36864u
#define U0        73728u
#define OFF_SK    (U0)
#define OFF_SV    (U0 + 16384u)
#define OFF_SQ    (U0)
#define OFF_XSH   (U0 + 32768u)
#define OFF_XSL   (U0 + 41984u)
#define OFF_V     (U0 + 51200u)    // kside V natural [64][72]
#define OFF_KP    (U0 + 60416u)    // kside k' [64][264]
#define OFF_RMK   (U0 + 94208u)    // [4][64] f32
#define OFF_QP    (U0 + 51200u)    // qside q' [64][264] (aliases V/KP)
#define OFF_KVT   (U0 + 84992u)
#define OFF_KSS   (U0 + 118784u)
#define OFF_RMQ   (U0 + 119808u)
#define OFF_DNI   (U0 + 120832u)
#define SMEM_TOTAL (U0 + 121088u)

__device__ float g_kv[BHp * Fp * Dp];
__device__ float g_ksum[BHp * Fp];
__device__ unsigned g_sync[BHp];
__device__ unsigned g_jobk;
__device__ unsigned g_jobq;

__global__ void zero_scratch() {
    int i = blockIdx.x * blockDim.x + threadIdx.x;
    if (i < BHp * Fp * Dp) g_kv[i] = 0.0f;
    if (i < BHp * Fp)      g_ksum[i] = 0.0f;
    if (i < BHp)           g_sync[i] = 0u;
    if (i == 0) { g_jobk = 0u; g_jobq = 0u; }
}

__device__ __forceinline__ void mma16816(float* c,
                                         unsigned a0, unsigned a1, unsigned a2, unsigned a3,
                                         unsigned b0, unsigned b1) {
    asm volatile(
        "mma.sync.aligned.m16n8k16.row.col.f32.f16.f16.f32 "
        "{%0,%1,%2,%3},{%4,%5,%6,%7},{%8,%9},{%0,%1,%2,%3};"
        : "+f"(c[0]), "+f"(c[1]), "+f"(c[2]), "+f"(c[3])
        : "r"(a0), "r"(a1), "r"(a2), "r"(a3), "r"(b0), "r"(b1));
}
__device__ __forceinline__ void ldsm4(unsigned* r, uint32_t a) {
    asm volatile("ldmatrix.sync.aligned.m8n8.x4.shared.b16 {%0,%1,%2,%3}, [%4];"
        : "=r"(r[0]), "=r"(r[1]), "=r"(r[2]), "=r"(r[3]) : "r"(a));
}
__device__ __forceinline__ void ldsm2(unsigned* r, uint32_t a) {
    asm volatile("ldmatrix.sync.aligned.m8n8.x2.shared.b16 {%0,%1}, [%2];"
        : "=r"(r[0]), "=r"(r[1]) : "r"(a));
}
__device__ __forceinline__ void ldsm4t(unsigned* r, uint32_t a) {
    asm volatile("ldmatrix.sync.aligned.m8n8.x4.trans.shared.b16 {%0,%1,%2,%3}, [%4];"
        : "=r"(r[0]), "=r"(r[1]), "=r"(r[2]), "=r"(r[3]) : "r"(a));
}
__device__ __forceinline__ void ldsm2t(unsigned* r, uint32_t a) {
    asm volatile("ldmatrix.sync.aligned.m8n8.x2.trans.shared.b16 {%0,%1}, [%2];"
        : "=r"(r[0]), "=r"(r[1]) : "r"(a));
}

__device__ __forceinline__ void cpasync16(void* dst_smem, const void* src) {
    uint32_t d = (uint32_t)__cvta_generic_to_shared(dst_smem);
    asm volatile("cp.async.cg.shared.global [%0], [%1], 16;" :: "r"(d), "l"(src));
}
#define CP_COMMIT() asm volatile("cp.async.commit_group;" ::: "memory")
#define CP_WAIT0()  asm volatile("cp.async.wait_group 0;" ::: "memory")

__device__ __forceinline__ void load_PT(const float* __restrict__ P,
                                        __half* PTh, __half* PTl, int tid) {
    for (int j = tid; j < Dp * Fp / 4; j += NT) {
        float4 v = ((const float4*)P)[j];
        int d = j >> 6;
        int f0 = (j & 63) * 4;
        #pragma unroll
        for (int u = 0; u < 4; u++) {
            float x = (&v.x)[u];
            __half hi = __float2half_rn(x);
            __half lo = __float2half_rn(x - __half2float(hi));
            PTh[(f0 + u) * PT_S + d] = hi;
            PTl[(f0 + u) * PT_S + d] = lo;
        }
    }
}

// ldmatrix lane-constant byte offsets
__device__ __forceinline__ int a4_const(int lane, int S) {          // non-trans A
    return 2 * (((lane & 7) + ((lane >> 3) & 1) * 8) * S + (lane >> 4) * 8);
}
__device__ __forceinline__ int b2_const(int lane, int S) {          // non-trans B
    return 2 * ((lane & 7) * S + ((lane >> 3) & 1) * 8);
}
__device__ __forceinline__ int a4t_const(int lane, int S) {         // trans A from [k][m]
    return 2 * ((lane & 7) * S) + (((lane >> 3) & 1) * 16) + (((lane >> 4) & 1) * 2 * 8 * S);
}
__device__ __forceinline__ int b2t_const(int lane, int S) {         // trans B from [k][n]
    int l = lane & 15;
    return 2 * ((l & 7) * S) + ((l >> 3) * 2 * 8 * S);
}

// 3-term projection, warp tile m32 x f64, ldmatrix loads
__device__ __forceinline__ void proj_mma(uint32_t xsh, uint32_t xsl,
                                         uint32_t pth, uint32_t ptl,
                                         int m0, int fbase, int a4c, int b2c,
                                         float pr[2][8][4]) {
    #pragma unroll
    for (int mi = 0; mi < 2; mi++)
        #pragma unroll
        for (int t = 0; t < 8; t++) {
            pr[mi][t][0] = 0.f; pr[mi][t][1] = 0.f; pr[mi][t][2] = 0.f; pr[mi][t][3] = 0.f;
        }
    #pragma unroll
    for (int k0 = 0; k0 < 64; k0 += 16) {
        unsigned ah[2][4], al[2][4];
        #pragma unroll
        for (int mi = 0; mi < 2; mi++) {
            uint32_t ab = 2u * ((m0 + mi * 16) * XS_S + k0) + a4c;
            ldsm4(ah[mi], xsh + ab);
            ldsm4(al[mi], xsl + ab);
        }
        #pragma unroll
        for (int t = 0; t < 8; t++) {
            uint32_t bb = 2u * ((fbase + t * 8) * PT_S + k0) + b2c;
            unsigned bh[2], bl[2];
            ldsm2(bh, pth + bb);
            ldsm2(bl, ptl + bb);
            #pragma unroll
            for (int mi = 0; mi < 2; mi++) {
                mma16816(pr[mi][t], ah[mi][0], ah[mi][1], ah[mi][2], ah[mi][3], bh[0], bh[1]);
                mma16816(pr[mi][t], ah[mi][0], ah[mi][1], ah[mi][2], ah[mi][3], bl[0], bl[1]);
                mma16816(pr[mi][t], al[mi][0], al[mi][1], al[mi][2], al[mi][3], bh[0], bh[1]);
            }
        }
    }
}

__device__ __forceinline__ void rowmax_store(float pr[2][8][4], float* RMAX,
                                             int m0, int seg, int lane) {
    const int r = lane >> 2;
    #pragma unroll
    for (int mi = 0; mi < 2; mi++) {
        float mlo = -3.4e38f, mhi = -3.4e38f;
        #pragma unroll
        for (int t = 0; t < 8; t++) {
            mlo = fmaxf(mlo, fmaxf(pr[mi][t][0], pr[mi][t][1]));
            mhi = fmaxf(mhi, fmaxf(pr[mi][t][2], pr[mi][t][3]));
        }
        #pragma unroll
        for (int off = 1; off <= 2; off <<= 1) {
            mlo = fmaxf(mlo, __shfl_xor_sync(0xffffffffu, mlo, off));
            mhi = fmaxf(mhi, __shfl_xor_sync(0xffffffffu, mhi, off));
        }
        if ((lane & 3) == 0) {
            RMAX[seg * 64 + m0 + mi * 16 + r]     = mlo;
            RMAX[seg * 64 + m0 + mi * 16 + 8 + r] = mhi;
        }
    }
}

__device__ __forceinline__ float rmax4(const float* RMAX, int row) {
    return fmaxf(fmaxf(RMAX[row], RMAX[64 + row]),
                 fmaxf(RMAX[128 + row], RMAX[192 + row]));
}

__device__ __forceinline__ unsigned pack2(__half a, __half b) {
    __half2 h = __halves2half2(a, b);
    return *(unsigned*)&h;
}

// ---------------------------------------------------------------------------
__device__ void kside_job(const float* __restrict__ K, const float* __restrict__ V,
                          int pair, int grp, char* sm, uint32_t smu,
                          int tid, int w, int lane) {
    __half* XSh = (__half*)(sm + OFF_XSH);
    __half* XSl = (__half*)(sm + OFF_XSL);
    __half* Vs  = (__half*)(sm + OFF_V);
    __half* KP  = (__half*)(sm + OFF_KP);
    float*  RMAX = (float*)(sm + OFF_RMK);
    float4* SK = (float4*)(sm + OFF_SK);
    float4* SV = (float4*)(sm + OFF_SV);

    const uint32_t xsh_u = smu + OFF_XSH, xsl_u = smu + OFF_XSL;
    const uint32_t pth_u = smu + OFF_PTH, ptl_u = smu + OFF_PTL;
    const uint32_t v_u   = smu + OFF_V,   kp_u  = smu + OFF_KP;

    const int r  = lane >> 2;
    const int q2 = (lane & 3) * 2;
    const int a4c72  = a4_const(lane, 72);
    const int b2c72  = b2_const(lane, 72);
    const int at4    = a4t_const(lane, KP_S);
    const int bt2    = b2t_const(lane, V_S);

    {
        const float4* ksrc = (const float4*)(K + ((size_t)pair * Np + grp * ROWS_PER_GROUP) * Dp);
        const float4* vsrc = (const float4*)(V + ((size_t)pair * Np + grp * ROWS_PER_GROUP) * Dp);
        #pragma unroll
        for (int i = 0; i < 4; i++) {
            int j = tid + NT * i;
            cpasync16(&SK[j], &ksrc[j]);
            cpasync16(&SV[j], &vsrc[j]);
        }
        CP_COMMIT();
    }

    // warp owns kv f-rows [w*32, w*32+32); t=8 tile is ksum (ones column)
    float accv[2][9][4];
    #pragma unroll
    for (int mi = 0; mi < 2; mi++)
        #pragma unroll
        for (int t = 0; t < 9; t++)
            #pragma unroll
            for (int u = 0; u < 4; u++) accv[mi][t][u] = 0.f;

    for (int c = 0; c < CHUNKS_PER_GROUP; c++) {
        CP_WAIT0();
        __syncthreads();

        // convert: X -> hi/lo packed, V natural [r][e] packed; ones col e=64
        #pragma unroll
        for (int i = 0; i < 4; i++) {
            int j = tid + NT * i;
            float4 xv = SK[j];
            float4 vv = SV[j];
            int rr = j >> 4;
            int d0 = (j & 15) * 4;
            __half h[4], l[4], vh[4];
            #pragma unroll
            for (int u = 0; u < 4; u++) {
                float x = (&xv.x)[u];
                h[u] = __float2half_rn(x);
                l[u] = __float2half_rn(x - __half2float(h[u]));
                vh[u] = __float2half_rn((&vv.x)[u]);
            }
            uint2 xh2 = make_uint2(pack2(h[0], h[1]), pack2(h[2], h[3]));
            uint2 xl2 = make_uint2(pack2(l[0], l[1]), pack2(l[2], l[3]));
            uint2 vv2 = make_uint2(pack2(vh[0], vh[1]), pack2(vh[2], vh[3]));
            *(uint2*)(XSh + rr * XS_S + d0) = xh2;
            *(uint2*)(XSl + rr * XS_S + d0) = xl2;
            *(uint2*)(Vs + rr * V_S + d0)   = vv2;
        }
        if (tid < CHUNK) {
            // ones column e=64, zeros e=65..71
            uint4 z = make_uint4(pack2(__float2half_rn(1.0f), __float2half_rn(0.0f)),
                                 pack2(__float2half_rn(0.0f), __float2half_rn(0.0f)),
                                 pack2(__float2half_rn(0.0f), __float2half_rn(0.0f)),
                                 pack2(__float2half_rn(0.0f), __float2half_rn(0.0f)));
            *(uint4*)(Vs + tid * V_S + 64) = z;
        }
        __syncthreads();

        if (c + 1 < CHUNKS_PER_GROUP) {
            const int row1 = grp * ROWS_PER_GROUP + (c + 1) * CHUNK;
            const float4* ksrc = (const float4*)(K + ((size_t)pair * Np + row1) * Dp);
            const float4* vsrc = (const float4*)(V + ((size_t)pair * Np + row1) * Dp);
            #pragma unroll
            for (int i = 0; i < 4; i++) {
                int j = tid + NT * i;
                cpasync16(&SK[j], &ksrc[j]);
                cpasync16(&SV[j], &vsrc[j]);
            }
            CP_COMMIT();
        }

        const int m0 = (w >> 2) * 32;
        const int seg = w & 3;
        const int fbase = seg * 64;
        float pr[2][8][4];
        proj_mma(xsh_u, xsl_u, pth_u, ptl_u, m0, fbase, a4c72, b2c72, pr);
        rowmax_store(pr, RMAX, m0, seg, lane);
        __syncthreads();

        // exp + ROW-MAJOR store KP[row][f] (conflict-free half2)
        #pragma unroll
        for (int mi = 0; mi < 2; mi++) {
            const int mrow = m0 + mi * 16;
            const float Mlo = rmax4(RMAX, mrow + r);
            const float Mhi = rmax4(RMAX, mrow + 8 + r);
            #pragma unroll
            for (int t = 0; t < 8; t++) {
                const int f = fbase + t * 8 + q2;
                __half2 lo2 = __floats2half2_rn(__expf(pr[mi][t][0] - Mlo) * 0.0625f,
                                                __expf(pr[mi][t][1] - Mlo) * 0.0625f);
                __half2 hi2 = __floats2half2_rn(__expf(pr[mi][t][2] - Mhi) * 0.0625f,
                                                __expf(pr[mi][t][3] - Mhi) * 0.0625f);
                *(__half2*)(KP + (mrow + r) * KP_S + f)     = lo2;
                *(__half2*)(KP + (mrow + 8 + r) * KP_S + f) = hi2;
            }
        }
        __syncthreads();

        // kv += k'^T v : A via ldsm4.trans from KP[r][f], B via ldsm2.trans from Vs[r][e]
        const int fw = w * 32;
        #pragma unroll
        for (int k0 = 0; k0 < 64; k0 += 16) {
            unsigned a[2][4];
            ldsm4t(a[0], kp_u + 2u * (k0 * KP_S + fw) + at4);
            ldsm4t(a[1], kp_u + 2u * (k0 * KP_S + fw + 16) + at4);
            #pragma unroll
            for (int t = 0; t < 9; t++) {
                unsigned b[2];
                ldsm2t(b, v_u + 2u * (k0 * V_S + t * 8) + bt2);
                mma16816(accv[0][t], a[0][0], a[0][1], a[0][2], a[0][3], b[0], b[1]);
                mma16816(accv[1][t], a[1][0], a[1][1], a[1][2], a[1][3], b[0], b[1]);
            }
        }
    }

    float* kvg = g_kv + (size_t)pair * Fp * Dp;
    #pragma unroll
    for (int mi = 0; mi < 2; mi++) {
        const int f0 = w * 32 + mi * 16 + r;
        #pragma unroll
        for (int t = 0; t < 8; t++) {
            const int e = t * 8 + q2;
            atomicAdd(&kvg[f0 * Dp + e],           accv[mi][t][0]);
            atomicAdd(&kvg[f0 * Dp + e + 1],       accv[mi][t][1]);
            atomicAdd(&kvg[(f0 + 8) * Dp + e],     accv[mi][t][2]);
            atomicAdd(&kvg[(f0 + 8) * Dp + e + 1], accv[mi][t][3]);
        }
        if ((lane & 3) == 0) {   // ksum lives in t=8 tile, e-column 64 (q2==0, u 0/2)
            atomicAdd(&g_ksum[(size_t)pair * Fp + f0],     accv[mi][8][0]);
            atomicAdd(&g_ksum[(size_t)pair * Fp + f0 + 8], accv[mi][8][2]);
        }
    }

    __syncthreads();
    __threadfence();
    if (tid == 0) atomicAdd(&g_sync[pair], 1u);
}

// ---------------------------------------------------------------------------
__device__ void qside_job(const float* __restrict__ Q, float* __restrict__ out,
                          int pair, int grp, bool reload_kv, char* sm, uint32_t smu,
                          int tid, int w, int lane) {
    __half* XSh = (__half*)(sm + OFF_XSH);
    __half* XSl = (__half*)(sm + OFF_XSL);
    __half* QP  = (__half*)(sm + OFF_QP);
    __half* KVTh = (__half*)(sm + OFF_KVT);
    float*  KSS  = (float*)(sm + OFF_KSS);
    float*  RMAX = (float*)(sm + OFF_RMQ);
    float*  DNI  = (float*)(sm + OFF_DNI);
    float4* SQ   = (float4*)(sm + OFF_SQ);

    const uint32_t xsh_u = smu + OFF_XSH, xsl_u = smu + OFF_XSL;
    const uint32_t pth_u = smu + OFF_PTH, ptl_u = smu + OFF_PTL;
    const uint32_t qp_u  = smu + OFF_QP,  kvt_u = smu + OFF_KVT;

    const int r  = lane >> 2;
    const int q2 = (lane & 3) * 2;
    const int a4c72  = a4_const(lane, 72);
    const int b2c72  = b2_const(lane, 72);
    const int a4c264 = a4_const(lane, 264);
    const int b2c264 = b2_const(lane, 264);

    {
        const float4* qsrc = (const float4*)(Q + ((size_t)pair * Np + grp * ROWS_PER_GROUP) * Dp);
        #pragma unroll
        for (int i = 0; i < 4; i++) {
            int j = tid + NT * i;
            cpasync16(&SQ[j], &qsrc[j]);
        }
        CP_COMMIT();
    }

    if (reload_kv) {
        const float4* kvg = (const float4*)(g_kv + (size_t)pair * Fp * Dp);
        for (int j = tid; j < Fp * Dp / 4; j += NT) {
            float4 v = __ldcg(&kvg[j]);
            int f = j >> 4;
            int e0 = (j & 15) * 4;
            #pragma unroll
            for (int u = 0; u < 4; u++)
                KVTh[(e0 + u) * KVT_S + f] = __float2half_rn((&v.x)[u]);
        }
        KSS[tid] = __ldcg(&g_ksum[(size_t)pair * Fp + tid]) + 1e-6f;
    }

    for (int c = 0; c < CHUNKS_PER_GROUP; c++) {
        CP_WAIT0();
        __syncthreads();

        #pragma unroll
        for (int i = 0; i < 4; i++) {
            int j = tid + NT * i;
            float4 xv = SQ[j];
            int rr = j >> 4;
            int d0 = (j & 15) * 4;
            __half h[4], l[4];
            #pragma unroll
            for (int u = 0; u < 4; u++) {
                float x = (&xv.x)[u];
                h[u] = __float2half_rn(x);
                l[u] = __float2half_rn(x - __half2float(h[u]));
            }
            uint2 xh2 = make_uint2(pack2(h[0], h[1]), pack2(h[2], h[3]));
            uint2 xl2 = make_uint2(pack2(l[0], l[1]), pack2(l[2], l[3]));
            *(uint2*)(XSh + rr * XS_S + d0) = xh2;
            *(uint2*)(XSl + rr * XS_S + d0) = xl2;
        }
        __syncthreads();

        if (c + 1 < CHUNKS_PER_GROUP) {
            const int row1 = grp * ROWS_PER_GROUP + (c + 1) * CHUNK;
            const float4* qsrc = (const float4*)(Q + ((size_t)pair * Np + row1) * Dp);
            #pragma unroll
            for (int i = 0; i < 4; i++) {
                int j = tid + NT * i;
                cpasync16(&SQ[j], &qsrc[j]);
            }
            CP_COMMIT();
        }

        const int m0 = (w >> 2) * 32;
        const int seg = w & 3;
        const int fbase = seg * 64;
        float pr[2][8][4];
        proj_mma(xsh_u, xsl_u, pth_u, ptl_u, m0, fbase, a4c72, b2c72, pr);
        rowmax_store(pr, RMAX, m0, seg, lane);
        __syncthreads();

        #pragma unroll
        for (int mi = 0; mi < 2; mi++) {
            const int mrow = m0 + mi * 16;
            const float Mlo = rmax4(RMAX, mrow + r);
            const float Mhi = rmax4(RMAX, mrow + 8 + r);
            #pragma unroll
            for (int t = 0; t < 8; t++) {
                const int f = fbase + t * 8 + q2;
                __half2 lo2 = __floats2half2_rn(__expf(pr[mi][t][0] - Mlo) * 0.0625f,
                                                __expf(pr[mi][t][1] - Mlo) * 0.0625f);
                __half2 hi2 = __floats2half2_rn(__expf(pr[mi][t][2] - Mhi) * 0.0625f,
                                                __expf(pr[mi][t][3] - Mhi) * 0.0625f);
                *(__half2*)(QP + (mrow + r) * QP_S + f)     = lo2;
                *(__half2*)(QP + (mrow + 8 + r) * QP_S + f) = hi2;
            }
        }
        __syncthreads();

        // denom: warp w owns rows w*8..w*8+7
        {
            #pragma unroll
            for (int rr = 0; rr < 8; rr++) {
                const int row = w * 8 + rr;
                float s = 0.f;
                #pragma unroll
                for (int j = 0; j < 8; j++) {
                    const int f = lane + 32 * j;
                    s = fmaf(__half2float(QP[row * QP_S + f]), KSS[f], s);
                }
                #pragma unroll
                for (int off = 16; off > 0; off >>= 1)
                    s += __shfl_xor_sync(0xffffffffu, s, off);
                if (lane == 0) DNI[row] = 1.0f / s;
            }
        }

        // out mma: rows [om0,om0+16), cols [nb,nb+32)
        const int om0 = (w >> 1) * 16;
        const int nb  = (w & 1) * 32;
        float oc[4][4];
        #pragma unroll
        for (int t = 0; t < 4; t++)
            #pragma unroll
            for (int u = 0; u < 4; u++) oc[t][u] = 0.f;

        #pragma unroll
        for (int k0 = 0; k0 < 256; k0 += 16) {
            unsigned a[4];
            ldsm4(a, qp_u + 2u * (om0 * QP_S + k0) + a4c264);
            #pragma unroll
            for (int t = 0; t < 4; t++) {
                unsigned b[2];
                ldsm2(b, kvt_u + 2u * ((nb + t * 8) * KVT_S + k0) + b2c264);
                mma16816(oc[t], a[0], a[1], a[2], a[3], b[0], b[1]);
            }
        }
        __syncthreads();   // DNI visible

        float* od = out + ((size_t)pair * Np + grp * ROWS_PER_GROUP + c * CHUNK) * Dp;
        const float ilo = DNI[om0 + r];
        const float ihi = DNI[om0 + 8 + r];
        #pragma unroll
        for (int t = 0; t < 4; t++) {
            const int e = nb + t * 8 + q2;
            float2 v0 = make_float2(oc[t][0] * ilo, oc[t][1] * ilo);
            float2 v1 = make_float2(oc[t][2] * ihi, oc[t][3] * ihi);
            *(float2*)&od[(om0 + r) * Dp + e]     = v0;
            *(float2*)&od[(om0 + 8 + r) * Dp + e] = v1;
        }
    }
}

// ---------------------------------------------------------------------------
__global__ __launch_bounds__(NT, 1)
void fused_kernel(const float* __restrict__ Q, const float* __restrict__ K,
                  const float* __restrict__ V, const float* __restrict__ P,
                  float* __restrict__ out) {
    extern __shared__ char sm[];
    __shared__ int jobS;

    const int tid  = threadIdx.x;
    const int w    = tid >> 5;
    const int lane = tid & 31;
    const uint32_t smu = (uint32_t)__cvta_generic_to_shared(sm);

    load_PT(P, (__half*)(sm + OFF_PTH), (__half*)(sm + OFF_PTL), tid);
    __syncthreads();

    for (;;) {
        if (tid == 0) jobS = (int)atomicAdd(&g_jobk, 1u);
        __syncthreads();
        const int j = jobS;
        if (j >= NJOBS) break;
        kside_job(K, V, j / GROUPS, j % GROUPS, sm, smu, tid, w, lane);
        __syncthreads();
    }

    int prev_pair = -1;
    for (;;) {
        if (tid == 0) jobS = (int)atomicAdd(&g_jobq, 1u);
        __syncthreads();
        const int j = jobS;
        if (j >= NJOBS) break;
        const int pair = j / GROUPS;
        const int grp  = j % GROUPS;
        const bool reload = (pair != prev_pair);
        if (reload) {
            if (tid == 0) {
                while (atomicAdd(&g_sync[pair], 0u) < (unsigned)GROUPS) __nanosleep(100);
            }
            __syncthreads();
            __threadfence();
            prev_pair = pair;
        }
        qside_job(Q, out, pair, grp, reload, sm, smu, tid, w, lane);
        __syncthreads();
    }
}

// ---------------------------------------------------------------------------
extern "C" void kernel_launch(void* const* d_in, const int* in_sizes, int n_in,
                              void* d_out, int out_size) {
    const float* q = (const float*)d_in[0];
    const float* k = (const float*)d_in[1];
    const float* v = (const float*)d_in[2];
    const float* p = (const float*)d_in[3];
    float* out = (float*)d_out;

    cudaFuncSetAttribute(fused_kernel, cudaFuncAttributeMaxDynamicSharedMemorySize, (int)SMEM_TOTAL);

    {
        int total = BHp * Fp * Dp;
        zero_scratch<<<(total + 255) / 256, 256>>>();
    }
    fused_kernel<<<NCTA, NT, SMEM_TOTAL>>>(q, k, v, p, out);
}

// round 15
// speedup vs baseline: 1.0690x; 1.0042x over previous
#include <cuda_runtime.h>
#include <cuda_fp16.h>
#include <cstdint>

// Problem constants: B=2,H=16,N=4096,D=64,F=256
#define BHp   32
#define Np    4096
#define Dp    64
#define Fp    256
#define CHUNK 64
#define GROUPS 16
#define ROWS_PER_GROUP 256
#define CHUNKS_PER_GROUP 4
#define NJOBS (BHp * GROUPS)
#define NCTA  148
#define NT    512

// smem strides (in halves)
#define XS_S  72
#define PT_S  72
#define V_S   72
#define KP_S  264
#define QP_S  264
#define KVT_S 264

// smem byte offsets
#define OFF_PTH   0u
#define OFF_PTL   36864u
#define U0        73728u
#define OFF_SK    (U0)
#define OFF_SV    (U0 + 16384u)
#define OFF_SQ    (U0)
#define OFF_XSH   (U0 + 32768u)
#define OFF_XSL   (U0 + 41984u)
#define OFF_V     (U0 + 51200u)    // kside V natural [64][72]
#define OFF_KP    (U0 + 60416u)    // kside k' [64][264]
#define OFF_RMK   (U0 + 94208u)    // [4][64] f32
#define OFF_QP    (U0 + 51200u)    // qside q' [64][264] (aliases V/KP)
#define OFF_KVT   (U0 + 84992u)
#define OFF_KSS   (U0 + 118784u)
#define OFF_RMQ   (U0 + 119808u)
#define OFF_DNI   (U0 + 120832u)
#define SMEM_TOTAL (U0 + 121088u)

__device__ float g_kv[BHp * Fp * Dp];
__device__ float g_ksum[BHp * Fp];
__device__ unsigned g_sync[BHp];
__device__ unsigned g_jobk;
__device__ unsigned g_jobq;

__global__ void zero_scratch() {
    int i = blockIdx.x * blockDim.x + threadIdx.x;
    if (i < BHp * Fp * Dp) g_kv[i] = 0.0f;
    if (i < BHp * Fp)      g_ksum[i] = 0.0f;
    if (i < BHp)           g_sync[i] = 0u;
    if (i == 0) { g_jobk = 0u; g_jobq = 0u; }
}

__device__ __forceinline__ void mma16816(float* c,
                                         unsigned a0, unsigned a1, unsigned a2, unsigned a3,
                                         unsigned b0, unsigned b1) {
    asm volatile(
        "mma.sync.aligned.m16n8k16.row.col.f32.f16.f16.f32 "
        "{%0,%1,%2,%3},{%4,%5,%6,%7},{%8,%9},{%0,%1,%2,%3};"
        : "+f"(c[0]), "+f"(c[1]), "+f"(c[2]), "+f"(c[3])
        : "r"(a0), "r"(a1), "r"(a2), "r"(a3), "r"(b0), "r"(b1));
}
__device__ __forceinline__ void ldsm4(unsigned* r, uint32_t a) {
    asm volatile("ldmatrix.sync.aligned.m8n8.x4.shared.b16 {%0,%1,%2,%3}, [%4];"
        : "=r"(r[0]), "=r"(r[1]), "=r"(r[2]), "=r"(r[3]) : "r"(a));
}
__device__ __forceinline__ void ldsm2(unsigned* r, uint32_t a) {
    asm volatile("ldmatrix.sync.aligned.m8n8.x2.shared.b16 {%0,%1}, [%2];"
        : "=r"(r[0]), "=r"(r[1]) : "r"(a));
}
__device__ __forceinline__ void ldsm4t(unsigned* r, uint32_t a) {
    asm volatile("ldmatrix.sync.aligned.m8n8.x4.trans.shared.b16 {%0,%1,%2,%3}, [%4];"
        : "=r"(r[0]), "=r"(r[1]), "=r"(r[2]), "=r"(r[3]) : "r"(a));
}
__device__ __forceinline__ void ldsm2t(unsigned* r, uint32_t a) {
    asm volatile("ldmatrix.sync.aligned.m8n8.x2.trans.shared.b16 {%0,%1}, [%2];"
        : "=r"(r[0]), "=r"(r[1]) : "r"(a));
}

__device__ __forceinline__ void cpasync16(void* dst_smem, const void* src) {
    uint32_t d = (uint32_t)__cvta_generic_to_shared(dst_smem);
    asm volatile("cp.async.cg.shared.global [%0], [%1], 16;" :: "r"(d), "l"(src));
}
#define CP_COMMIT() asm volatile("cp.async.commit_group;" ::: "memory")
#define CP_WAIT0()  asm volatile("cp.async.wait_group 0;" ::: "memory")

__device__ __forceinline__ void load_PT(const float* __restrict__ P,
                                        __half* PTh, __half* PTl, int tid) {
    for (int j = tid; j < Dp * Fp / 4; j += NT) {
        float4 v = ((const float4*)P)[j];
        int d = j >> 6;
        int f0 = (j & 63) * 4;
        #pragma unroll
        for (int u = 0; u < 4; u++) {
            float x = (&v.x)[u];
            __half hi = __float2half_rn(x);
            __half lo = __float2half_rn(x - __half2float(hi));
            PTh[(f0 + u) * PT_S + d] = hi;
            PTl[(f0 + u) * PT_S + d] = lo;
        }
    }
}

// ldmatrix lane-constant byte offsets
__device__ __forceinline__ int a4_const(int lane, int S) {          // non-trans A
    return 2 * (((lane & 7) + ((lane >> 3) & 1) * 8) * S + (lane >> 4) * 8);
}
__device__ __forceinline__ int b2_const(int lane, int S) {          // non-trans B
    return 2 * ((lane & 7) * S + ((lane >> 3) & 1) * 8);
}
__device__ __forceinline__ int a4t_const(int lane, int S) {         // trans A from [k][m]
    return 2 * ((lane & 7) * S) + (((lane >> 3) & 1) * 16) + (((lane >> 4) & 1) * 2 * 8 * S);
}
__device__ __forceinline__ int b2t_const(int lane, int S) {         // trans B from [k][n]
    int l = lane & 15;
    return 2 * ((l & 7) * S) + ((l >> 3) * 2 * 8 * S);
}

// 3-term projection, warp tile m16 x f64, ldmatrix loads
__device__ __forceinline__ void proj_mma(uint32_t xsh, uint32_t xsl,
                                         uint32_t pth, uint32_t ptl,
                                         int m0, int fbase, int a4c, int b2c,
                                         float pr[8][4]) {
    #pragma unroll
    for (int t = 0; t < 8; t++) {
        pr[t][0] = 0.f; pr[t][1] = 0.f; pr[t][2] = 0.f; pr[t][3] = 0.f;
    }
    #pragma unroll
    for (int k0 = 0; k0 < 64; k0 += 16) {
        unsigned ah[4], al[4];
        uint32_t ab = 2u * (m0 * XS_S + k0) + a4c;
        ldsm4(ah, xsh + ab);
        ldsm4(al, xsl + ab);
        #pragma unroll
        for (int t = 0; t < 8; t++) {
            uint32_t bb = 2u * ((fbase + t * 8) * PT_S + k0) + b2c;
            unsigned bh[2], bl[2];
            ldsm2(bh, pth + bb);
            ldsm2(bl, ptl + bb);
            mma16816(pr[t], ah[0], ah[1], ah[2], ah[3], bh[0], bh[1]);
            mma16816(pr[t], ah[0], ah[1], ah[2], ah[3], bl[0], bl[1]);
            mma16816(pr[t], al[0], al[1], al[2], al[3], bh[0], bh[1]);
        }
    }
}

// Row-max partials for one (m16, seg) tile -> RMAX[seg][64]
__device__ __forceinline__ void rowmax_store(float pr[8][4], float* RMAX,
                                             int m0, int seg, int lane) {
    const int r = lane >> 2;
    float mlo = -3.4e38f, mhi = -3.4e38f;
    #pragma unroll
    for (int t = 0; t < 8; t++) {
        mlo = fmaxf(mlo, fmaxf(pr[t][0], pr[t][1]));
        mhi = fmaxf(mhi, fmaxf(pr[t][2], pr[t][3]));
    }
    #pragma unroll
    for (int off = 1; off <= 2; off <<= 1) {
        mlo = fmaxf(mlo, __shfl_xor_sync(0xffffffffu, mlo, off));
        mhi = fmaxf(mhi, __shfl_xor_sync(0xffffffffu, mhi, off));
    }
    if ((lane & 3) == 0) {
        RMAX[seg * 64 + m0 + r]     = mlo;
        RMAX[seg * 64 + m0 + 8 + r] = mhi;
    }
}

__device__ __forceinline__ float rmax4(const float* RMAX, int row) {
    return fmaxf(fmaxf(RMAX[row], RMAX[64 + row]),
                 fmaxf(RMAX[128 + row], RMAX[192 + row]));
}

__device__ __forceinline__ unsigned pack2(__half a, __half b) {
    __half2 h = __halves2half2(a, b);
    return *(unsigned*)&h;
}

// ---------------------------------------------------------------------------
__device__ void kside_job(const float* __restrict__ K, const float* __restrict__ V,
                          int pair, int grp, char* sm, uint32_t smu,
                          int tid, int w, int lane) {
    __half* XSh = (__half*)(sm + OFF_XSH);
    __half* XSl = (__half*)(sm + OFF_XSL);
    __half* Vs  = (__half*)(sm + OFF_V);
    __half* KP  = (__half*)(sm + OFF_KP);
    float*  RMAX = (float*)(sm + OFF_RMK);
    float4* SK = (float4*)(sm + OFF_SK);
    float4* SV = (float4*)(sm + OFF_SV);

    const uint32_t xsh_u = smu + OFF_XSH, xsl_u = smu + OFF_XSL;
    const uint32_t pth_u = smu + OFF_PTH, ptl_u = smu + OFF_PTL;
    const uint32_t v_u   = smu + OFF_V,   kp_u  = smu + OFF_KP;

    const int r  = lane >> 2;
    const int q2 = (lane & 3) * 2;
    const int a4c72  = a4_const(lane, 72);
    const int b2c72  = b2_const(lane, 72);
    const int at4    = a4t_const(lane, KP_S);
    const int bt2    = b2t_const(lane, V_S);

    {
        const float4* ksrc = (const float4*)(K + ((size_t)pair * Np + grp * ROWS_PER_GROUP) * Dp);
        const float4* vsrc = (const float4*)(V + ((size_t)pair * Np + grp * ROWS_PER_GROUP) * Dp);
        #pragma unroll
        for (int i = 0; i < 2; i++) {
            int j = tid + NT * i;
            cpasync16(&SK[j], &ksrc[j]);
            cpasync16(&SV[j], &vsrc[j]);
        }
        CP_COMMIT();
    }
    // ones column e=64 (+ zero pad) — region untouched by per-chunk converts
    if (tid < CHUNK) {
        uint4 z = make_uint4(pack2(__float2half_rn(1.0f), __float2half_rn(0.0f)),
                             pack2(__float2half_rn(0.0f), __float2half_rn(0.0f)),
                             pack2(__float2half_rn(0.0f), __float2half_rn(0.0f)),
                             pack2(__float2half_rn(0.0f), __float2half_rn(0.0f)));
        *(uint4*)(Vs + tid * V_S + 64) = z;
    }

    // warp owns kv f-rows [w*16, w*16+16); t=8 tile is ksum (ones column)
    float accv[9][4];
    #pragma unroll
    for (int t = 0; t < 9; t++)
        #pragma unroll
        for (int u = 0; u < 4; u++) accv[t][u] = 0.f;

    for (int c = 0; c < CHUNKS_PER_GROUP; c++) {
        CP_WAIT0();
        __syncthreads();

        // convert: X -> hi/lo packed, V natural [r][e] packed
        #pragma unroll
        for (int i = 0; i < 2; i++) {
            int j = tid + NT * i;
            float4 xv = SK[j];
            float4 vv = SV[j];
            int rr = j >> 4;
            int d0 = (j & 15) * 4;
            __half h[4], l[4], vh[4];
            #pragma unroll
            for (int u = 0; u < 4; u++) {
                float x = (&xv.x)[u];
                h[u] = __float2half_rn(x);
                l[u] = __float2half_rn(x - __half2float(h[u]));
                vh[u] = __float2half_rn((&vv.x)[u]);
            }
            *(uint2*)(XSh + rr * XS_S + d0) = make_uint2(pack2(h[0], h[1]), pack2(h[2], h[3]));
            *(uint2*)(XSl + rr * XS_S + d0) = make_uint2(pack2(l[0], l[1]), pack2(l[2], l[3]));
            *(uint2*)(Vs + rr * V_S + d0)   = make_uint2(pack2(vh[0], vh[1]), pack2(vh[2], vh[3]));
        }
        __syncthreads();

        if (c + 1 < CHUNKS_PER_GROUP) {
            const int row1 = grp * ROWS_PER_GROUP + (c + 1) * CHUNK;
            const float4* ksrc = (const float4*)(K + ((size_t)pair * Np + row1) * Dp);
            const float4* vsrc = (const float4*)(V + ((size_t)pair * Np + row1) * Dp);
            #pragma unroll
            for (int i = 0; i < 2; i++) {
                int j = tid + NT * i;
                cpasync16(&SK[j], &ksrc[j]);
                cpasync16(&SV[j], &vsrc[j]);
            }
            CP_COMMIT();
        }

        const int m0 = (w >> 2) * 16;
        const int seg = w & 3;
        const int fbase = seg * 64;
        float pr[8][4];
        proj_mma(xsh_u, xsl_u, pth_u, ptl_u, m0, fbase, a4c72, b2c72, pr);
        rowmax_store(pr, RMAX, m0, seg, lane);
        __syncthreads();

        // exp + ROW-MAJOR store KP[row][f]
        {
            const float Mlo = rmax4(RMAX, m0 + r);
            const float Mhi = rmax4(RMAX, m0 + 8 + r);
            #pragma unroll
            for (int t = 0; t < 8; t++) {
                const int f = fbase + t * 8 + q2;
                __half2 lo2 = __floats2half2_rn(__expf(pr[t][0] - Mlo) * 0.0625f,
                                                __expf(pr[t][1] - Mlo) * 0.0625f);
                __half2 hi2 = __floats2half2_rn(__expf(pr[t][2] - Mhi) * 0.0625f,
                                                __expf(pr[t][3] - Mhi) * 0.0625f);
                *(__half2*)(KP + (m0 + r) * KP_S + f)     = lo2;
                *(__half2*)(KP + (m0 + 8 + r) * KP_S + f) = hi2;
            }
        }
        __syncthreads();

        // kv += k'^T v : warp owns f-rows [w*16, w*16+16)
        const int fw = w * 16;
        #pragma unroll
        for (int k0 = 0; k0 < 64; k0 += 16) {
            unsigned a[4];
            ldsm4t(a, kp_u + 2u * (k0 * KP_S + fw) + at4);
            #pragma unroll
            for (int t = 0; t < 9; t++) {
                unsigned b[2];
                ldsm2t(b, v_u + 2u * (k0 * V_S + t * 8) + bt2);
                mma16816(accv[t], a[0], a[1], a[2], a[3], b[0], b[1]);
            }
        }
    }

    float* kvg = g_kv + (size_t)pair * Fp * Dp;
    {
        const int f0 = w * 16 + r;
        #pragma unroll
        for (int t = 0; t < 8; t++) {
            const int e = t * 8 + q2;
            atomicAdd(&kvg[f0 * Dp + e],           accv[t][0]);
            atomicAdd(&kvg[f0 * Dp + e + 1],       accv[t][1]);
            atomicAdd(&kvg[(f0 + 8) * Dp + e],     accv[t][2]);
            atomicAdd(&kvg[(f0 + 8) * Dp + e + 1], accv[t][3]);
        }
        if ((lane & 3) == 0) {   // ksum: t=8 tile, e-column 64
            atomicAdd(&g_ksum[(size_t)pair * Fp + f0],     accv[8][0]);
            atomicAdd(&g_ksum[(size_t)pair * Fp + f0 + 8], accv[8][2]);
        }
    }

    __syncthreads();
    __threadfence();
    if (tid == 0) atomicAdd(&g_sync[pair], 1u);
}

// ---------------------------------------------------------------------------
__device__ void qside_job(const float* __restrict__ Q, float* __restrict__ out,
                          int pair, int grp, bool reload_kv, char* sm, uint32_t smu,
                          int tid, int w, int lane) {
    __half* XSh = (__half*)(sm + OFF_XSH);
    __half* XSl = (__half*)(sm + OFF_XSL);
    __half* QP  = (__half*)(sm + OFF_QP);
    __half* KVTh = (__half*)(sm + OFF_KVT);
    float*  KSS  = (float*)(sm + OFF_KSS);
    float*  RMAX = (float*)(sm + OFF_RMQ);
    float*  DNI  = (float*)(sm + OFF_DNI);
    float4* SQ   = (float4*)(sm + OFF_SQ);

    const uint32_t xsh_u = smu + OFF_XSH, xsl_u = smu + OFF_XSL;
    const uint32_t pth_u = smu + OFF_PTH, ptl_u = smu + OFF_PTL;
    const uint32_t qp_u  = smu + OFF_QP,  kvt_u = smu + OFF_KVT;

    const int r  = lane >> 2;
    const int q2 = (lane & 3) * 2;
    const int a4c72  = a4_const(lane, 72);
    const int b2c72  = b2_const(lane, 72);
    const int a4c264 = a4_const(lane, 264);
    const int b2c264 = b2_const(lane, 264);

    {
        const float4* qsrc = (const float4*)(Q + ((size_t)pair * Np + grp * ROWS_PER_GROUP) * Dp);
        #pragma unroll
        for (int i = 0; i < 2; i++) {
            int j = tid + NT * i;
            cpasync16(&SQ[j], &qsrc[j]);
        }
        CP_COMMIT();
    }

    if (reload_kv) {
        const float4* kvg = (const float4*)(g_kv + (size_t)pair * Fp * Dp);
        for (int j = tid; j < Fp * Dp / 4; j += NT) {
            float4 v = __ldcg(&kvg[j]);
            int f = j >> 4;
            int e0 = (j & 15) * 4;
            #pragma unroll
            for (int u = 0; u < 4; u++)
                KVTh[(e0 + u) * KVT_S + f] = __float2half_rn((&v.x)[u]);
        }
        if (tid < Fp) KSS[tid] = __ldcg(&g_ksum[(size_t)pair * Fp + tid]) + 1e-6f;
    }

    for (int c = 0; c < CHUNKS_PER_GROUP; c++) {
        CP_WAIT0();
        __syncthreads();

        #pragma unroll
        for (int i = 0; i < 2; i++) {
            int j = tid + NT * i;
            float4 xv = SQ[j];
            int rr = j >> 4;
            int d0 = (j & 15) * 4;
            __half h[4], l[4];
            #pragma unroll
            for (int u = 0; u < 4; u++) {
                float x = (&xv.x)[u];
                h[u] = __float2half_rn(x);
                l[u] = __float2half_rn(x - __half2float(h[u]));
            }
            *(uint2*)(XSh + rr * XS_S + d0) = make_uint2(pack2(h[0], h[1]), pack2(h[2], h[3]));
            *(uint2*)(XSl + rr * XS_S + d0) = make_uint2(pack2(l[0], l[1]), pack2(l[2], l[3]));
        }
        __syncthreads();

        if (c + 1 < CHUNKS_PER_GROUP) {
            const int row1 = grp * ROWS_PER_GROUP + (c + 1) * CHUNK;
            const float4* qsrc = (const float4*)(Q + ((size_t)pair * Np + row1) * Dp);
            #pragma unroll
            for (int i = 0; i < 2; i++) {
                int j = tid + NT * i;
                cpasync16(&SQ[j], &qsrc[j]);
            }
            CP_COMMIT();
        }

        const int m0 = (w >> 2) * 16;
        const int seg = w & 3;
        const int fbase = seg * 64;
        float pr[8][4];
        proj_mma(xsh_u, xsl_u, pth_u, ptl_u, m0, fbase, a4c72, b2c72, pr);
        rowmax_store(pr, RMAX, m0, seg, lane);
        __syncthreads();

        {
            const float Mlo = rmax4(RMAX, m0 + r);
            const float Mhi = rmax4(RMAX, m0 + 8 + r);
            #pragma unroll
            for (int t = 0; t < 8; t++) {
                const int f = fbase + t * 8 + q2;
                __half2 lo2 = __floats2half2_rn(__expf(pr[t][0] - Mlo) * 0.0625f,
                                                __expf(pr[t][1] - Mlo) * 0.0625f);
                __half2 hi2 = __floats2half2_rn(__expf(pr[t][2] - Mhi) * 0.0625f,
                                                __expf(pr[t][3] - Mhi) * 0.0625f);
                *(__half2*)(QP + (m0 + r) * QP_S + f)     = lo2;
                *(__half2*)(QP + (m0 + 8 + r) * QP_S + f) = hi2;
            }
        }
        __syncthreads();

        // denom: warp w owns rows [w*4, w*4+4)
        {
            #pragma unroll
            for (int rr = 0; rr < 4; rr++) {
                const int row = w * 4 + rr;
                float s = 0.f;
                #pragma unroll
                for (int j = 0; j < 8; j++) {
                    const int f = lane + 32 * j;
                    s = fmaf(__half2float(QP[row * QP_S + f]), KSS[f], s);
                }
                #pragma unroll
                for (int off = 16; off > 0; off >>= 1)
                    s += __shfl_xor_sync(0xffffffffu, s, off);
                if (lane == 0) DNI[row] = 1.0f / s;
            }
        }

        // out mma: rows [om0,om0+16), cols [nb,nb+16)
        const int om0 = (w >> 2) * 16;
        const int nb  = (w & 3) * 16;
        float oc[2][4];
        #pragma unroll
        for (int t = 0; t < 2; t++)
            #pragma unroll
            for (int u = 0; u < 4; u++) oc[t][u] = 0.f;

        #pragma unroll
        for (int k0 = 0; k0 < 256; k0 += 16) {
            unsigned a[4];
            ldsm4(a, qp_u + 2u * (om0 * QP_S + k0) + a4c264);
            #pragma unroll
            for (int t = 0; t < 2; t++) {
                unsigned b[2];
                ldsm2(b, kvt_u + 2u * ((nb + t * 8) * KVT_S + k0) + b2c264);
                mma16816(oc[t], a[0], a[1], a[2], a[3], b[0], b[1]);
            }
        }
        __syncthreads();   // DNI visible

        float* od = out + ((size_t)pair * Np + grp * ROWS_PER_GROUP + c * CHUNK) * Dp;
        const float ilo = DNI[om0 + r];
        const float ihi = DNI[om0 + 8 + r];
        #pragma unroll
        for (int t = 0; t < 2; t++) {
            const int e = nb + t * 8 + q2;
            float2 v0 = make_float2(oc[t][0] * ilo, oc[t][1] * ilo);
            float2 v1 = make_float2(oc[t][2] * ihi, oc[t][3] * ihi);
            *(float2*)&od[(om0 + r) * Dp + e]     = v0;
            *(float2*)&od[(om0 + 8 + r) * Dp + e] = v1;
        }
    }
}

// ---------------------------------------------------------------------------
__global__ __launch_bounds__(NT, 1)
void fused_kernel(const float* __restrict__ Q, const float* __restrict__ K,
                  const float* __restrict__ V, const float* __restrict__ P,
                  float* __restrict__ out) {
    extern __shared__ char sm[];
    __shared__ int jobS;

    const int tid  = threadIdx.x;
    const int w    = tid >> 5;
    const int lane = tid & 31;
    const uint32_t smu = (uint32_t)__cvta_generic_to_shared(sm);

    load_PT(P, (__half*)(sm + OFF_PTH), (__half*)(sm + OFF_PTL), tid);
    __syncthreads();

    for (;;) {
        if (tid == 0) jobS = (int)atomicAdd(&g_jobk, 1u);
        __syncthreads();
        const int j = jobS;
        if (j >= NJOBS) break;
        kside_job(K, V, j / GROUPS, j % GROUPS, sm, smu, tid, w, lane);
        __syncthreads();
    }

    int prev_pair = -1;
    for (;;) {
        if (tid == 0) jobS = (int)atomicAdd(&g_jobq, 1u);
        __syncthreads();
        const int j = jobS;
        if (j >= NJOBS) break;
        const int pair = j / GROUPS;
        const int grp  = j % GROUPS;
        const bool reload = (pair != prev_pair);
        if (reload) {
            if (tid == 0) {
                while (atomicAdd(&g_sync[pair], 0u) < (unsigned)GROUPS) __nanosleep(100);
            }
            __syncthreads();
            __threadfence();
            prev_pair = pair;
        }
        qside_job(Q, out, pair, grp, reload, sm, smu, tid, w, lane);
        __syncthreads();
    }
}

// ---------------------------------------------------------------------------
extern "C" void kernel_launch(void* const* d_in, const int* in_sizes, int n_in,
                              void* d_out, int out_size) {
    const float* q = (const float*)d_in[0];
    const float* k = (const float*)d_in[1];
    const float* v = (const float*)d_in[2];
    const float* p = (const float*)d_in[3];
    float* out = (float*)d_out;

    cudaFuncSetAttribute(fused_kernel, cudaFuncAttributeMaxDynamicSharedMemorySize, (int)SMEM_TOTAL);

    {
        int total = BHp * Fp * Dp;
        zero_scratch<<<(total + 255) / 256, 256>>>();
    }
    fused_kernel<<<NCTA, NT, SMEM_TOTAL>>>(q, k, v, p, out);
}